// round 10
// baseline (speedup 1.0000x reference)
#include <cuda_runtime.h>
#include <cstdint>

#define BB 4096
#define NN 8192
#define DD 512
#define RR 4
#define NBLK (BB / 2)    // 2048 blocks: each handles pairs (r, r+B) for 2 values of r

__device__ float g_partial[NBLK];

__device__ __forceinline__ const float* row_ptr(const float* zi, const float* zj, int r) {
    return (r < BB) ? (zi + (size_t)r * DD) : (zj + (size_t)(r - BB) * DD);
}

__device__ __forceinline__ void cp16(uint32_t dst_smem, const float* src) {
    asm volatile("cp.async.cg.shared.global [%0], [%1], 16;"
                 :: "r"(dst_smem), "l"(src));
}

// Block = 4 warps = 4 rows: {r0, r0+B, r1, r1+B} with r0=2*bid, r1=2*bid+1.
// Warp w's positive partner is warp (w^1)'s row -> its x-buffer & x2 are shared.
// All rows staged global->smem via cp.async (MLP=20/lane, zero register cost).
__global__ void __launch_bounds__(128) fused_kernel(const float* __restrict__ zi,
                                                    const float* __restrict__ zj,
                                                    const int* __restrict__ neg_idx) {
    __shared__ float4 x_buf[4][DD / 4];          // 8 KB: each warp's own row
    __shared__ float4 n_buf[4][RR][DD / 4];      // 32 KB: each warp's 4 negatives
    __shared__ float  s_x2[4];
    __shared__ float  s_nll[4];

    int warp = threadIdx.x >> 5;
    int lane = threadIdx.x & 31;
    int r0   = blockIdx.x * 2 + (warp >> 1);           // pair id
    int row  = (warp & 1) ? (r0 + BB) : r0;            // w0:r0  w1:r0+B  w2:r1  w3:r1+B

    // Negative indices (uniform across warp)
    int4 nv = *reinterpret_cast<const int4*>(neg_idx + row * RR);
    int neg[RR];
    neg[0] = nv.x + (nv.x >= row ? 1 : 0);
    neg[1] = nv.y + (nv.y >= row ? 1 : 0);
    neg[2] = nv.z + (nv.z >= row ? 1 : 0);
    neg[3] = nv.w + (nv.w >= row ? 1 : 0);

    // ---- stage own row + 4 negatives: 20 cp.async/lane, one group ----
    {
        const float* gx = row_ptr(zi, zj, row);
        uint32_t dx = (uint32_t)__cvta_generic_to_shared(&x_buf[warp][lane]);
#pragma unroll
        for (int k = 0; k < 4; k++)
            cp16(dx + k * 32 * 16, gx + lane * 4 + k * 128);
#pragma unroll
        for (int p = 0; p < RR; p++) {
            const float* gn = row_ptr(zi, zj, neg[p]);
            uint32_t dn = (uint32_t)__cvta_generic_to_shared(&n_buf[warp][p][lane]);
#pragma unroll
            for (int k = 0; k < 4; k++)
                cp16(dn + k * 32 * 16, gn + lane * 4 + k * 128);
        }
        asm volatile("cp.async.commit_group;");
        asm volatile("cp.async.wait_group 0;" ::: "memory");
    }

    // ---- own row into regs + x2 ----
    float4 x[4];
#pragma unroll
    for (int k = 0; k < 4; k++) x[k] = x_buf[warp][lane + 32 * k];

    float x2 = 0.0f;
#pragma unroll
    for (int k = 0; k < 4; k++)
        x2 += x[k].x * x[k].x + x[k].y * x[k].y + x[k].z * x[k].z + x[k].w * x[k].w;
#pragma unroll
    for (int o = 16; o; o >>= 1) x2 += __shfl_xor_sync(0xFFFFFFFFu, x2, o);
    if (lane == 0) s_x2[warp] = x2;

    __syncthreads();   // paired x_buf + s_x2 ready for everyone

    // ---- positive dot (partner = paired warp's x buffer) ----
    float pdot = 0.0f;
#pragma unroll
    for (int k = 0; k < 4; k++) {
        float4 b = x_buf[warp ^ 1][lane + 32 * k];
        float4 a = x[k];
        pdot += a.x * b.x + a.y * b.y + a.z * b.z + a.w * b.w;
    }

    // ---- negative dots + their norms ----
    float dot[RR], y2[RR];
#pragma unroll
    for (int p = 0; p < RR; p++) {
        float d = 0.0f, n = 0.0f;
#pragma unroll
        for (int k = 0; k < 4; k++) {
            float4 b = n_buf[warp][p][lane + 32 * k];
            float4 a = x[k];
            d += a.x * b.x + a.y * b.y + a.z * b.z + a.w * b.w;
            n += b.x * b.x + b.y * b.y + b.z * b.z + b.w * b.w;
        }
        dot[p] = d;
        y2[p]  = n;
    }

#pragma unroll
    for (int o = 16; o; o >>= 1) {
        pdot += __shfl_xor_sync(0xFFFFFFFFu, pdot, o);
#pragma unroll
        for (int p = 0; p < RR; p++) {
            dot[p] += __shfl_xor_sync(0xFFFFFFFFu, dot[p], o);
            y2[p]  += __shfl_xor_sync(0xFFFFFFFFu, y2[p], o);
        }
    }

    if (lane == 0) {
        const float invT = 1.0f / (0.5f + 1e-8f);
        float rnx = 1.0f / fmaxf(sqrtf(x2), 1e-8f);
        float l[5];
        {
            float rny = 1.0f / fmaxf(sqrtf(s_x2[warp ^ 1]), 1e-8f);
            l[0] = pdot * rnx * rny * invT;
        }
#pragma unroll
        for (int p = 0; p < RR; p++) {
            float rny = 1.0f / fmaxf(sqrtf(y2[p]), 1e-8f);
            l[p + 1] = dot[p] * rnx * rny * invT;
        }
        float m = l[0];
#pragma unroll
        for (int p = 1; p < 5; p++) m = fmaxf(m, l[p]);
        float se = 0.0f;
#pragma unroll
        for (int p = 0; p < 5; p++) se += expf(l[p] - m);
        s_nll[warp] = m + logf(se) - l[0];
    }
    __syncthreads();

    if (threadIdx.x == 0) {
        float partial = s_nll[0] + s_nll[1] + s_nll[2] + s_nll[3];
        asm volatile("st.global.cg.f32 [%0], %1;"
                     :: "l"(&g_partial[blockIdx.x]), "f"(partial) : "memory");
    }
}

// Deterministic reduce of 2048 block partials -> mean. 1 block, 256 threads,
// vectorized L2 reads (partials were written with st.cg).
__global__ void reduce_kernel(float* __restrict__ out) {
    __shared__ float ws[8];
    int tid = threadIdx.x;
    const float4* p4 = reinterpret_cast<const float4*>(g_partial);
    float4 a = p4[tid];
    float4 b = p4[tid + 256];
    float s = a.x + a.y + a.z + a.w + b.x + b.y + b.z + b.w;
#pragma unroll
    for (int o = 16; o; o >>= 1) s += __shfl_xor_sync(0xFFFFFFFFu, s, o);
    if ((tid & 31) == 0) ws[tid >> 5] = s;
    __syncthreads();
    if (tid < 32) {
        float t = (tid < 8) ? ws[tid] : 0.0f;
#pragma unroll
        for (int o = 4; o; o >>= 1) t += __shfl_xor_sync(0xFFFFFFFFu, t, o);
        if (tid == 0) out[0] = t * (1.0f / (float)NN);
    }
}

extern "C" void kernel_launch(void* const* d_in, const int* in_sizes, int n_in,
                              void* d_out, int out_size) {
    const float* zi      = (const float*)d_in[0];
    const float* zj      = (const float*)d_in[1];
    const int*   neg_idx = (const int*)d_in[2];
    float* out = (float*)d_out;

    fused_kernel<<<NBLK, 128>>>(zi, zj, neg_idx);
    reduce_kernel<<<1, 256>>>(out);
}